// round 3
// baseline (speedup 1.0000x reference)
#include <cuda_runtime.h>
#include <cuda_fp16.h>
#include <math.h>

#define BATCH 8
#define CH 64
#define HIN 224
#define WIN 224
#define PLANE (HIN*WIN)         /* 50176 */
#define NPLANES (BATCH*CH)      /* 512 */
#define CMID 32
#define PH 64
#define PW 128
#define POOLED_ELEMS (BATCH*CH*PH*PW)  /* 4194304 */
#define SMEM_C (PLANE*2 + 512*4 + 256) /* fp16 plane + inner results */

// ---------------- device scratch ----------------
__device__ float  g_branch[NPLANES];       // per-(b,c) mean
__device__ float  g_lohi[BATCH*2];
__device__ float  g_cval[NPLANES];         // constant-region bilinear value
__device__ float2 g_coords[BATCH*64*128];  // (ix,iy) per (b,i,j)
__device__ int2   g_rows[BATCH];           // sampled row range per batch

// ------------- kernel 1: per-plane mean (pure streaming read) -----------
__global__ void __launch_bounds__(512) k_mean(const float* __restrict__ x) {
    __shared__ float sm[16];
    int p = blockIdx.x;
    int tid = threadIdx.x;
    const float4* xp = (const float4*)x + (size_t)p * (PLANE / 4);
    float s = 0.f;
#pragma unroll 7
    for (int i = tid; i < PLANE / 4; i += 512) {
        float4 v = xp[i];
        s += (v.x + v.y) + (v.z + v.w);
    }
#pragma unroll
    for (int o = 16; o > 0; o >>= 1) s += __shfl_xor_sync(~0u, s, o);
    if ((tid & 31) == 0) sm[tid >> 5] = s;
    __syncthreads();
    if (tid < 16) {
        s = sm[tid];
#pragma unroll
        for (int o = 8; o > 0; o >>= 1) s += __shfl_xor_sync(0xffffu, s, o);
        if (tid == 0) g_branch[p] = s * (1.0f / (float)PLANE);
    }
}

// ------------- kernel 2: MLP + cval + coords + row range (1 block) ------
__global__ void __launch_bounds__(256) k_mlp_coords(
        const float* __restrict__ l,
        const float* __restrict__ w1, const float* __restrict__ b1,
        const float* __restrict__ w2, const float* __restrict__ b2,
        const float* __restrict__ x,
        float* __restrict__ outw) {
    __shared__ float br[NPLANES];
    __shared__ float hid[BATCH][CMID];
    __shared__ float wgt[16];
    __shared__ float lohi[16];
    __shared__ int smin[BATCH], smax[BATCH];
    int tid = threadIdx.x;

    br[tid] = g_branch[tid];
    br[tid + 256] = g_branch[tid + 256];
    if (tid < BATCH) { smin[tid] = 1 << 30; smax[tid] = -1; }
    __syncthreads();

    // hidden = relu(branch @ w1 + b1)
    {
        int b = tid >> 5, m = tid & 31;
        float s = b1[m];
#pragma unroll
        for (int c = 0; c < CH; c++) s += br[b * CH + c] * w1[c * CMID + m];
        hid[b][m] = fmaxf(s, 0.f);
    }
    __syncthreads();
    if (tid < 16) {
        int b = tid >> 1, k = tid & 1;
        float s = b2[k];
#pragma unroll
        for (int m = 0; m < CMID; m++) s += hid[b][m] * w2[m * 2 + k];
        float wv = 1.f / (1.f + expf(-s));
        wgt[2 * b + k] = wv;
        outw[tid] = wv;
    }
    __syncthreads();
    if (tid < BATCH) {
        lohi[2 * tid + 0] = logf(wgt[2 * tid + 0] * 0.01f);
        lohi[2 * tid + 1] = logf(wgt[2 * tid + 1] * 0.60f);
        g_lohi[2 * tid + 0] = lohi[2 * tid + 0];
        g_lohi[2 * tid + 1] = lohi[2 * tid + 1];
    }
    __syncthreads();

    // constant-region bilinear values
#pragma unroll
    for (int rep = 0; rep < 2; rep++) {
        int idx = rep * 256 + tid;
        int b = idx >> 6, c = idx & 63;
        float gx = l[2 * b], gy = l[2 * b + 1];
        float ix = fminf(fmaxf((gx + 1.f) * 112.f - 0.5f, 0.f), 223.f);
        float iy = fminf(fmaxf((gy + 1.f) * 112.f - 0.5f, 0.f), 223.f);
        float x0f = floorf(ix), y0f = floorf(iy);
        float wx = ix - x0f, wy = iy - y0f;
        int x0 = (int)x0f, y0 = (int)y0f;
        int x1 = min(x0 + 1, 223), y1 = min(y0 + 1, 223);
        const float* pp = x + (size_t)idx * PLANE;
        g_cval[idx] = pp[y0 * 224 + x0] * (1.f - wx) * (1.f - wy)
                    + pp[y0 * 224 + x1] * wx * (1.f - wy)
                    + pp[y1 * 224 + x0] * (1.f - wx) * wy
                    + pp[y1 * 224 + x1] * wx * wy;
    }

    // coordinate table + per-batch row range
    int tmin[BATCH], tmax[BATCH];
#pragma unroll
    for (int b = 0; b < BATCH; b++) { tmin[b] = 1 << 30; tmax[b] = -1; }
    for (int e = tid; e < 8192; e += 256) {
        int i = e >> 7, j = e & 127;
        float xg = (i - 32) * (1.0f / 32.0f);
        float yg = (j - 64) * (1.0f / 64.0f);
        float logr = logf(fmaxf(sqrtf(xg * xg + yg * yg), 1e-12f));
        float a = atan2f(yg, xg);
        if (!(a > 0.f)) a += 6.283185307179586f;
        float tgx = a * 0.3183098861837907f - 1.f;
#pragma unroll
        for (int b = 0; b < BATCH; b++) {
            float lo = lohi[2 * b], hi = lohi[2 * b + 1];
            float gx = tgx + l[2 * b];
            float gy = (logr - lo) * (2.f / (hi - lo)) - 1.f + l[2 * b + 1];
            float ix = fminf(fmaxf((gx + 1.f) * 112.f - 0.5f, 0.f), 223.f);
            float iy = fminf(fmaxf((gy + 1.f) * 112.f - 0.5f, 0.f), 223.f);
            g_coords[(b << 13) + e] = make_float2(ix, iy);
            int y0 = (int)floorf(iy);
            tmin[b] = min(tmin[b], y0);
            tmax[b] = max(tmax[b], min(y0 + 1, 223));
        }
    }
#pragma unroll
    for (int b = 0; b < BATCH; b++) {
        atomicMin(&smin[b], tmin[b]);
        atomicMax(&smax[b], tmax[b]);
    }
    __syncthreads();
    if (tid < BATCH) g_rows[tid] = make_int2(smin[tid], smax[tid]);
}

// ------------- kernel 3: per-plane SMEM sample + fill -------------------
__global__ void __launch_bounds__(256) k_sample(const float* __restrict__ x,
                                                float* __restrict__ out) {
    extern __shared__ char smem[];
    __half* sh  = (__half*)smem;                       // up to 224*224 fp16
    float* sres = (float*)(smem + PLANE * 2);          // 512 inner results

    int p = blockIdx.x;
    int b = p >> 6;
    int tid = threadIdx.x;
    int2 rr = g_rows[b];
    int rmin = rr.x;
    int n4 = (rr.y - rmin + 1) * 56;                   // float4 count

    const float4* xp = (const float4*)x + (size_t)p * (PLANE / 4) + rmin * 56;
    half2* shp = (half2*)sh;
    for (int i = tid; i < n4; i += 256) {
        float4 v = xp[i];
        shp[2 * i]     = __floats2half2_rn(v.x, v.y);
        shp[2 * i + 1] = __floats2half2_rn(v.z, v.w);
    }
    __syncthreads();

    const float2* co = g_coords + (b << 13);
#pragma unroll
    for (int r = 0; r < 2; r++) {
        int pos = (tid << 1) + r;
        int h = pos >> 5, w = pos & 31;
        float acc = 0.f;
#pragma unroll
        for (int s = 0; s < 16; s++) {
            int i = 4 * h + (s >> 2);
            int j = 4 * w + (s & 3);
            float2 c2 = co[(i << 7) + j];
            float x0f = floorf(c2.x), y0f = floorf(c2.y);
            float wx = c2.x - x0f, wy = c2.y - y0f;
            int x0 = (int)x0f, y0 = (int)y0f;
            int x1 = min(x0 + 1, 223), y1 = min(y0 + 1, 223);
            int r0 = (y0 - rmin) * 224, r1 = (y1 - rmin) * 224;
            float v00 = __half2float(sh[r0 + x0]);
            float v01 = __half2float(sh[r0 + x1]);
            float v10 = __half2float(sh[r1 + x0]);
            float v11 = __half2float(sh[r1 + x1]);
            acc += (v00 * (1.f - wx) + v01 * wx) * (1.f - wy)
                 + (v10 * (1.f - wx) + v11 * wx) * wy;
        }
        sres[pos] = acc * (1.f / 16.f);
    }
    __syncthreads();

    float cv = g_cval[p];
    float4* ob = (float4*)out + (size_t)p * 2048;
#pragma unroll
    for (int k = 0; k < 8; k++) {
        int idx = k * 256 + tid;
        int h = idx >> 5, w4 = idx & 31;
        float4 v;
        if (h < 16 && w4 < 8) {
            int base = h * 32 + w4 * 4;
            v = make_float4(sres[base], sres[base + 1], sres[base + 2], sres[base + 3]);
        } else {
            v = make_float4(cv, cv, cv, cv);
        }
        ob[idx] = v;
    }
}

// ---------------------------------------------------------------------
extern "C" void kernel_launch(void* const* d_in, const int* in_sizes, int n_in,
                              void* d_out, int out_size) {
    const float* x  = (const float*)d_in[0];
    const float* l  = (const float*)d_in[1];
    const float* w1 = (const float*)d_in[2];
    const float* b1 = (const float*)d_in[3];
    const float* w2 = (const float*)d_in[4];
    const float* b2 = (const float*)d_in[5];
    float* out  = (float*)d_out;
    float* outw = out + POOLED_ELEMS;

    cudaFuncSetAttribute(k_sample, cudaFuncAttributeMaxDynamicSharedMemorySize, SMEM_C);

    k_mean<<<NPLANES, 512>>>(x);
    k_mlp_coords<<<1, 256>>>(l, w1, b1, w2, b2, x, outw);
    k_sample<<<NPLANES, 256, SMEM_C>>>(x, out);
}

// round 4
// speedup vs baseline: 1.3140x; 1.3140x over previous
#include <cuda_runtime.h>
#include <cuda_fp16.h>
#include <math.h>

#define BATCH 8
#define CH 64
#define PLANE 50176            /* 224*224 */
#define NPLANES 512            /* BATCH*CH */
#define POOLED_ELEMS 4194304   /* 8*64*64*128 */
#define SMEM_SZ (PLANE*2 + 512*4)   /* fp16 plane + inner results = 102400 B */

// ---------------- device scratch ----------------
__device__ float  g_branch[NPLANES];
__device__ float  g_lohi[16];
__device__ float  g_cval[NPLANES];
__device__ float2 g_polar[8192];   // (logr, a/pi - 1) per (i,j)
__device__ int    g_ctr = 0;

// ------- K1: per-plane mean + polar table + cval + fan-in MLP -----------
__global__ void __launch_bounds__(512) k_mean(
        const float* __restrict__ x,
        const float* __restrict__ l,
        const float* __restrict__ w1, const float* __restrict__ b1,
        const float* __restrict__ w2, const float* __restrict__ b2,
        float* __restrict__ outw) {
    __shared__ float sm[16];
    __shared__ int isLast;
    int p = blockIdx.x, tid = threadIdx.x;

    // streaming plane sum
    const float4* xp = (const float4*)x + (size_t)p * 12544;
    float s0 = 0.f, s1 = 0.f;
    for (int i = tid; i < 12544; i += 512) {
        float4 v = xp[i];
        s0 += v.x + v.y; s1 += v.z + v.w;
    }
    float s = s0 + s1;
#pragma unroll
    for (int o = 16; o; o >>= 1) s += __shfl_xor_sync(~0u, s, o);
    if ((tid & 31) == 0) sm[tid >> 5] = s;
    __syncthreads();
    if (tid < 16) {
        s = sm[tid];
#pragma unroll
        for (int o = 8; o; o >>= 1) s += __shfl_xor_sync(0xffffu, s, o);
        if (tid == 0) g_branch[p] = s * (1.0f / (float)PLANE);
    }

    // block 0 side work: polar table + constant-region bilinear values
    if (p == 0) {
        for (int e = tid; e < 8192; e += 512) {
            int i = e >> 7, j = e & 127;
            float xg = (i - 32) * (1.0f / 32.0f);
            float yg = (j - 64) * (1.0f / 64.0f);
            float logr = logf(fmaxf(sqrtf(xg * xg + yg * yg), 1e-12f));
            float a = atan2f(yg, xg);
            if (!(a > 0.f)) a += 6.283185307179586f;
            g_polar[e] = make_float2(logr, a * 0.3183098861837907f - 1.f);
        }
        {
            int idx = tid;                 // 512 threads = 512 (b,c) pairs
            int b = idx >> 6;
            float gx = l[2 * b], gy = l[2 * b + 1];
            float ix = fminf(fmaxf((gx + 1.f) * 112.f - 0.5f, 0.f), 223.f);
            float iy = fminf(fmaxf((gy + 1.f) * 112.f - 0.5f, 0.f), 223.f);
            float x0f = floorf(ix), y0f = floorf(iy);
            float wx = ix - x0f, wy = iy - y0f;
            int x0 = (int)x0f, y0 = (int)y0f;
            int x1 = min(x0 + 1, 223), y1 = min(y0 + 1, 223);
            const float* pp = x + (size_t)idx * PLANE;
            g_cval[idx] = pp[y0 * 224 + x0] * (1.f - wx) * (1.f - wy)
                        + pp[y0 * 224 + x1] * wx * (1.f - wy)
                        + pp[y1 * 224 + x0] * (1.f - wx) * wy
                        + pp[y1 * 224 + x1] * wx * wy;
        }
    }

    // fan-in: last block to finish runs the MLP
    __threadfence();
    if (tid == 0) {
        int old = atomicAdd(&g_ctr, 1);
        isLast = (old == (int)gridDim.x - 1);
    }
    __syncthreads();
    if (!isLast) return;

    __shared__ float br[NPLANES];
    __shared__ float hid[BATCH][32];
    __shared__ float wgt[16];
    br[tid] = g_branch[tid];
    __syncthreads();
    if (tid < 256) {
        int b = tid >> 5, m = tid & 31;
        float acc = b1[m];
#pragma unroll
        for (int c = 0; c < 64; c++) acc += br[b * 64 + c] * w1[c * 32 + m];
        hid[b][m] = fmaxf(acc, 0.f);
    }
    __syncthreads();
    if (tid < 16) {
        int b = tid >> 1, k = tid & 1;
        float acc = b2[k];
#pragma unroll
        for (int m = 0; m < 32; m++) acc += hid[b][m] * w2[m * 2 + k];
        float wv = 1.f / (1.f + expf(-acc));
        wgt[tid] = wv;
        outw[tid] = wv;
    }
    __syncthreads();
    if (tid < 8) {
        g_lohi[2 * tid + 0] = logf(wgt[2 * tid + 0] * 0.01f);
        g_lohi[2 * tid + 1] = logf(wgt[2 * tid + 1] * 0.60f);
    }
    if (tid == 0) g_ctr = 0;     // reset for graph replay
}

// ------- K2: per-plane SMEM sample + fill (x expected L2-resident) ------
__global__ void __launch_bounds__(512) k_sample(const float* __restrict__ x,
                                                const float* __restrict__ l,
                                                float* __restrict__ out) {
    extern __shared__ char smem[];
    __half* sh  = (__half*)smem;               // 224*224 fp16 plane
    float* sres = (float*)(smem + PLANE * 2);  // 512 inner results

    int p = blockIdx.x, b = p >> 6, tid = threadIdx.x;

    // load plane -> fp16 smem (coalesced float4, L2-hit expected)
    const float4* xp = (const float4*)x + (size_t)p * 12544;
    uint2* shp = (uint2*)sh;
    for (int i = tid; i < 12544; i += 512) {
        float4 v = xp[i];
        half2 h0 = __floats2half2_rn(v.x, v.y);
        half2 h1 = __floats2half2_rn(v.z, v.w);
        uint2 u;
        u.x = *(unsigned int*)&h0;
        u.y = *(unsigned int*)&h1;
        shp[i] = u;
    }

    float l0 = l[2 * b], l1 = l[2 * b + 1];
    float lo = g_lohi[2 * b], hi = g_lohi[2 * b + 1];
    float inv2 = 2.f / (hi - lo);
    __syncthreads();

    // one pooled position per thread: 16 samples x 4 taps from smem
    int h = tid >> 5, w = tid & 31;
    float acc = 0.f;
#pragma unroll
    for (int s = 0; s < 16; s++) {
        int i = 4 * h + (s >> 2);
        int j = 4 * w + (s & 3);
        float2 pb = g_polar[(i << 7) | j];
        float gx = pb.y + l0;
        float gy = (pb.x - lo) * inv2 - 1.f + l1;
        float ix = fminf(fmaxf((gx + 1.f) * 112.f - 0.5f, 0.f), 223.f);
        float iy = fminf(fmaxf((gy + 1.f) * 112.f - 0.5f, 0.f), 223.f);
        float x0f = floorf(ix), y0f = floorf(iy);
        float wx = ix - x0f, wy = iy - y0f;
        int x0 = (int)x0f, y0 = (int)y0f;
        int x1 = min(x0 + 1, 223), y1 = min(y0 + 1, 223);
        int r0 = y0 * 224, r1 = y1 * 224;
        float v00 = __half2float(sh[r0 + x0]);
        float v01 = __half2float(sh[r0 + x1]);
        float v10 = __half2float(sh[r1 + x0]);
        float v11 = __half2float(sh[r1 + x1]);
        acc += (v00 * (1.f - wx) + v01 * wx) * (1.f - wy)
             + (v10 * (1.f - wx) + v11 * wx) * wy;
    }
    sres[tid] = acc * (1.f / 16.f);
    __syncthreads();

    // write full output plane: inner region from sres, rest constant fill
    float cv = g_cval[p];
    float4* ob = (float4*)out + (size_t)p * 2048;
#pragma unroll
    for (int k = 0; k < 4; k++) {
        int idx = k * 512 + tid;
        int hh = idx >> 5, w4 = idx & 31;
        float4 v;
        if (hh < 16 && w4 < 8) {
            int base = hh * 32 + w4 * 4;
            v = make_float4(sres[base], sres[base + 1], sres[base + 2], sres[base + 3]);
        } else {
            v = make_float4(cv, cv, cv, cv);
        }
        ob[idx] = v;
    }
}

// ---------------------------------------------------------------------
extern "C" void kernel_launch(void* const* d_in, const int* in_sizes, int n_in,
                              void* d_out, int out_size) {
    const float* x  = (const float*)d_in[0];
    const float* l  = (const float*)d_in[1];
    const float* w1 = (const float*)d_in[2];
    const float* b1 = (const float*)d_in[3];
    const float* w2 = (const float*)d_in[4];
    const float* b2 = (const float*)d_in[5];
    float* out  = (float*)d_out;
    float* outw = out + POOLED_ELEMS;

    cudaFuncSetAttribute(k_sample, cudaFuncAttributeMaxDynamicSharedMemorySize, SMEM_SZ);

    k_mean<<<NPLANES, 512>>>(x, l, w1, b1, w2, b2, outw);
    k_sample<<<NPLANES, 512, SMEM_SZ>>>(x, l, out);
}